// round 1
// baseline (speedup 1.0000x reference)
#include <cuda_runtime.h>
#include <cstdint>

#define B_  16
#define C_  256
#define HW  1024   // H*W = N tokens
#define N_  1024
#define D_  256
#define NG  4
#define GC  64     // channels per group

#define BM 64
#define BN 64
#define BK 16

// Scratch (static device globals — no allocation allowed)
__device__ float g_h[(size_t)B_ * C_ * HW];   // groupnorm out, [b][c][n]
__device__ float g_q[(size_t)B_ * N_ * D_];   // [b][n][d]
__device__ float g_k[(size_t)B_ * N_ * D_];
__device__ float g_v[(size_t)B_ * N_ * D_];
__device__ float g_s[(size_t)B_ * N_ * N_];   // scores / probs [b][n][m]
__device__ float g_o[(size_t)B_ * N_ * D_];   // attn out [b][n][d]

// ---------------------------------------------------------------------------
// 1. GroupNorm: per (group, batch) block; two passes over 64*1024 elements.
// ---------------------------------------------------------------------------
__global__ __launch_bounds__(256) void gn_kernel(const float* __restrict__ x,
                                                 const float* __restrict__ gamma,
                                                 const float* __restrict__ beta) {
    int g = blockIdx.x, b = blockIdx.y;
    const float* xp = x + ((size_t)b * C_ + (size_t)g * GC) * HW;
    float*       hp = g_h + ((size_t)b * C_ + (size_t)g * GC) * HW;
    const int n_el = GC * HW;  // 65536

    float s = 0.f, ss = 0.f;
    for (int i = threadIdx.x; i < n_el; i += 256) {
        float v = xp[i];
        s += v;
        ss += v * v;
    }
    __shared__ float sh1[256], sh2[256];
    sh1[threadIdx.x] = s;
    sh2[threadIdx.x] = ss;
    __syncthreads();
    for (int o = 128; o > 0; o >>= 1) {
        if (threadIdx.x < o) {
            sh1[threadIdx.x] += sh1[threadIdx.x + o];
            sh2[threadIdx.x] += sh2[threadIdx.x + o];
        }
        __syncthreads();
    }
    float mean = sh1[0] * (1.0f / n_el);
    float var  = sh2[0] * (1.0f / n_el) - mean * mean;
    float rstd = rsqrtf(var + 1e-5f);

    for (int i = threadIdx.x; i < n_el; i += 256) {
        int c = g * GC + (i >> 10);   // i / HW
        hp[i] = (xp[i] - mean) * rstd * gamma[c] + beta[c];
    }
}

// ---------------------------------------------------------------------------
// 2. QKV GEMM: out[b][n][d] = sum_c h[b][c][n] * W[d][c] + bias[d]
//    A layout [K=C][M=N] (m contig), B layout [N=D][K=C] (k contig).
// ---------------------------------------------------------------------------
__global__ __launch_bounds__(256) void qkv_kernel(const float* __restrict__ Wq,
                                                  const float* __restrict__ bq,
                                                  const float* __restrict__ Wk,
                                                  const float* __restrict__ bk,
                                                  const float* __restrict__ Wv,
                                                  const float* __restrict__ bv) {
    int mi = blockIdx.z % 3, b = blockIdx.z / 3;
    const float* W    = (mi == 0) ? Wq : (mi == 1) ? Wk : Wv;
    const float* bias = (mi == 0) ? bq : (mi == 1) ? bk : bv;
    float* out = ((mi == 0) ? g_q : (mi == 1) ? g_k : g_v) + (size_t)b * N_ * D_;
    const float* A = g_h + (size_t)b * C_ * HW;

    int m0 = blockIdx.y * BM;  // token n
    int n0 = blockIdx.x * BN;  // channel d

    __shared__ float As[BK][BM + 4];
    __shared__ float Bs[BK][BN + 4];
    int tx = threadIdx.x, ty = threadIdx.y;
    int tid = ty * 16 + tx;

    float acc[4][4] = {};

    for (int k0 = 0; k0 < C_; k0 += BK) {
        {   // A: h[k][m], m contiguous -> direct float4 tile
            int kk = tid >> 4, mm = (tid & 15) * 4;
            float4 v = *reinterpret_cast<const float4*>(&A[(size_t)(k0 + kk) * HW + m0 + mm]);
            *reinterpret_cast<float4*>(&As[kk][mm]) = v;
        }
        {   // B: W[d][c], c contiguous -> transposed store
            int nn = tid >> 2, kk = (tid & 3) * 4;
            float4 v = *reinterpret_cast<const float4*>(&W[(size_t)(n0 + nn) * C_ + k0 + kk]);
            Bs[kk + 0][nn] = v.x; Bs[kk + 1][nn] = v.y;
            Bs[kk + 2][nn] = v.z; Bs[kk + 3][nn] = v.w;
        }
        __syncthreads();
        #pragma unroll
        for (int k = 0; k < BK; k++) {
            float ra[4], rb[4];
            *reinterpret_cast<float4*>(ra) = *reinterpret_cast<const float4*>(&As[k][ty * 4]);
            *reinterpret_cast<float4*>(rb) = *reinterpret_cast<const float4*>(&Bs[k][tx * 4]);
            #pragma unroll
            for (int i = 0; i < 4; i++)
                #pragma unroll
                for (int j = 0; j < 4; j++)
                    acc[i][j] += ra[i] * rb[j];
        }
        __syncthreads();
    }
    #pragma unroll
    for (int i = 0; i < 4; i++) {
        int m = m0 + ty * 4 + i;
        #pragma unroll
        for (int j = 0; j < 4; j++) {
            int n = n0 + tx * 4 + j;
            out[(size_t)m * D_ + n] = acc[i][j] + bias[n];
        }
    }
}

// ---------------------------------------------------------------------------
// 3. Scores: S[b][n][m] = (1/16) * sum_d Q[b][n][d] * K[b][m][d]
//    Both A and B are [M/N][K] with K contiguous -> transposed tile loads.
// ---------------------------------------------------------------------------
__global__ __launch_bounds__(256) void score_kernel() {
    int b = blockIdx.z;
    const float* Q = g_q + (size_t)b * N_ * D_;
    const float* K = g_k + (size_t)b * N_ * D_;
    float*       S = g_s + (size_t)b * N_ * N_;
    int m0 = blockIdx.y * BM;  // query
    int n0 = blockIdx.x * BN;  // key

    __shared__ float As[BK][BM + 4];
    __shared__ float Bs[BK][BN + 4];
    int tx = threadIdx.x, ty = threadIdx.y;
    int tid = ty * 16 + tx;
    float acc[4][4] = {};

    for (int k0 = 0; k0 < D_; k0 += BK) {
        {
            int mm = tid >> 2, kk = (tid & 3) * 4;
            float4 v = *reinterpret_cast<const float4*>(&Q[(size_t)(m0 + mm) * D_ + k0 + kk]);
            As[kk + 0][mm] = v.x; As[kk + 1][mm] = v.y;
            As[kk + 2][mm] = v.z; As[kk + 3][mm] = v.w;
        }
        {
            int nn = tid >> 2, kk = (tid & 3) * 4;
            float4 v = *reinterpret_cast<const float4*>(&K[(size_t)(n0 + nn) * D_ + k0 + kk]);
            Bs[kk + 0][nn] = v.x; Bs[kk + 1][nn] = v.y;
            Bs[kk + 2][nn] = v.z; Bs[kk + 3][nn] = v.w;
        }
        __syncthreads();
        #pragma unroll
        for (int k = 0; k < BK; k++) {
            float ra[4], rb[4];
            *reinterpret_cast<float4*>(ra) = *reinterpret_cast<const float4*>(&As[k][ty * 4]);
            *reinterpret_cast<float4*>(rb) = *reinterpret_cast<const float4*>(&Bs[k][tx * 4]);
            #pragma unroll
            for (int i = 0; i < 4; i++)
                #pragma unroll
                for (int j = 0; j < 4; j++)
                    acc[i][j] += ra[i] * rb[j];
        }
        __syncthreads();
    }
    #pragma unroll
    for (int i = 0; i < 4; i++) {
        int m = m0 + ty * 4 + i;
        #pragma unroll
        for (int j = 0; j < 4; j++) {
            int n = n0 + tx * 4 + j;
            S[(size_t)m * N_ + n] = acc[i][j] * 0.0625f;  // 1/sqrt(256)
        }
    }
}

// ---------------------------------------------------------------------------
// 4. Row softmax over m (row length 1024), one block (256 thr) per row.
// ---------------------------------------------------------------------------
__global__ __launch_bounds__(256) void softmax_kernel() {
    size_t row = blockIdx.x;
    float* S = g_s + row * N_;
    int t = threadIdx.x;

    float vals[4];
    float lm = -1e30f;
    #pragma unroll
    for (int i = 0; i < 4; i++) {
        vals[i] = S[t + i * 256];
        lm = fmaxf(lm, vals[i]);
    }
    __shared__ float sh[256];
    sh[t] = lm;
    __syncthreads();
    for (int o = 128; o > 0; o >>= 1) {
        if (t < o) sh[t] = fmaxf(sh[t], sh[t + o]);
        __syncthreads();
    }
    float m = sh[0];
    __syncthreads();

    float s = 0.f;
    #pragma unroll
    for (int i = 0; i < 4; i++) {
        vals[i] = __expf(vals[i] - m);
        s += vals[i];
    }
    sh[t] = s;
    __syncthreads();
    for (int o = 128; o > 0; o >>= 1) {
        if (t < o) sh[t] += sh[t + o];
        __syncthreads();
    }
    float inv = 1.0f / sh[0];
    #pragma unroll
    for (int i = 0; i < 4; i++) S[t + i * 256] = vals[i] * inv;
}

// ---------------------------------------------------------------------------
// 5. O = P @ V : O[b][n][d] = sum_m P[b][n][m] * V[b][m][d]
//    A layout [M][K] (k contig, transposed load); B layout [K][N] (n contig).
// ---------------------------------------------------------------------------
__global__ __launch_bounds__(256) void pv_kernel() {
    int b = blockIdx.z;
    const float* P = g_s + (size_t)b * N_ * N_;
    const float* V = g_v + (size_t)b * N_ * D_;
    float*       O = g_o + (size_t)b * N_ * D_;
    int m0 = blockIdx.y * BM;  // query n
    int n0 = blockIdx.x * BN;  // channel d

    __shared__ float As[BK][BM + 4];
    __shared__ float Bs[BK][BN + 4];
    int tx = threadIdx.x, ty = threadIdx.y;
    int tid = ty * 16 + tx;
    float acc[4][4] = {};

    for (int k0 = 0; k0 < N_; k0 += BK) {
        {
            int mm = tid >> 2, kk = (tid & 3) * 4;
            float4 v = *reinterpret_cast<const float4*>(&P[(size_t)(m0 + mm) * N_ + k0 + kk]);
            As[kk + 0][mm] = v.x; As[kk + 1][mm] = v.y;
            As[kk + 2][mm] = v.z; As[kk + 3][mm] = v.w;
        }
        {
            int kk = tid >> 4, nn = (tid & 15) * 4;
            float4 v = *reinterpret_cast<const float4*>(&V[(size_t)(k0 + kk) * D_ + n0 + nn]);
            *reinterpret_cast<float4*>(&Bs[kk][nn]) = v;
        }
        __syncthreads();
        #pragma unroll
        for (int k = 0; k < BK; k++) {
            float ra[4], rb[4];
            *reinterpret_cast<float4*>(ra) = *reinterpret_cast<const float4*>(&As[k][ty * 4]);
            *reinterpret_cast<float4*>(rb) = *reinterpret_cast<const float4*>(&Bs[k][tx * 4]);
            #pragma unroll
            for (int i = 0; i < 4; i++)
                #pragma unroll
                for (int j = 0; j < 4; j++)
                    acc[i][j] += ra[i] * rb[j];
        }
        __syncthreads();
    }
    #pragma unroll
    for (int i = 0; i < 4; i++) {
        int m = m0 + ty * 4 + i;
        #pragma unroll
        for (int j = 0; j < 4; j++) {
            int n = n0 + tx * 4 + j;
            O[(size_t)m * D_ + n] = acc[i][j];
        }
    }
}

// ---------------------------------------------------------------------------
// 6. Transpose back + residual: out[b][c][n] = O[b][n][c] + x[b][c][n]
// ---------------------------------------------------------------------------
__global__ __launch_bounds__(256) void ta_kernel(const float* __restrict__ x,
                                                 float* __restrict__ out) {
    __shared__ float tile[32][33];
    int b = blockIdx.z;
    int n0 = blockIdx.x * 32, c0 = blockIdx.y * 32;
    const float* O = g_o + (size_t)b * N_ * D_;
    int tx = threadIdx.x, ty = threadIdx.y;  // 32 x 8

    #pragma unroll
    for (int j = 0; j < 4; j++) {
        int r = ty + j * 8;
        tile[r][tx] = O[(size_t)(n0 + r) * D_ + c0 + tx];
    }
    __syncthreads();
    const float* xb = x + (size_t)b * C_ * HW;
    float*       ob = out + (size_t)b * C_ * HW;
    #pragma unroll
    for (int j = 0; j < 4; j++) {
        int r = ty + j * 8;
        size_t idx = (size_t)(c0 + r) * HW + n0 + tx;
        ob[idx] = tile[tx][r] + xb[idx];
    }
}

// ---------------------------------------------------------------------------
extern "C" void kernel_launch(void* const* d_in, const int* in_sizes, int n_in,
                              void* d_out, int out_size) {
    const float* x     = (const float*)d_in[0];
    const float* Wq    = (const float*)d_in[1];
    const float* bq    = (const float*)d_in[2];
    const float* Wk    = (const float*)d_in[3];
    const float* bk    = (const float*)d_in[4];
    const float* Wv    = (const float*)d_in[5];
    const float* bv    = (const float*)d_in[6];
    const float* gamma = (const float*)d_in[7];
    const float* beta  = (const float*)d_in[8];
    float* out = (float*)d_out;

    gn_kernel<<<dim3(NG, B_), 256>>>(x, gamma, beta);
    qkv_kernel<<<dim3(D_ / BN, N_ / BM, 3 * B_), dim3(16, 16)>>>(Wq, bq, Wk, bk, Wv, bv);
    score_kernel<<<dim3(N_ / BN, N_ / BM, B_), dim3(16, 16)>>>();
    softmax_kernel<<<B_ * N_, 256>>>();
    pv_kernel<<<dim3(D_ / BN, N_ / BM, B_), dim3(16, 16)>>>();
    ta_kernel<<<dim3(N_ / 32, C_ / 32, B_), dim3(32, 8)>>>(x, out);
}

// round 3
// speedup vs baseline: 3.5466x; 3.5466x over previous
#include <cuda_runtime.h>
#include <cuda_bf16.h>
#include <cstdint>

#define B_  16
#define C_  256
#define N_  1024
#define NG  4
#define GC  64

typedef __nv_bfloat16 bf16;

// ---- scratch (static device globals) ----
__device__ bf16  g_hT[(size_t)B_ * N_ * C_];   // groupnorm out, [b][n][c]
__device__ bf16  g_q [(size_t)B_ * N_ * C_];   // [b][n][d], pre-scaled by 1/16
__device__ bf16  g_k [(size_t)B_ * N_ * C_];
__device__ bf16  g_vt[(size_t)B_ * C_ * N_];   // V transposed: [b][d][m]
__device__ float g_s [(size_t)B_ * N_ * N_];   // scores fp32 [b][m][n]
__device__ bf16  g_p [(size_t)B_ * N_ * N_];   // probs bf16 [b][m][n]
__device__ bf16  g_wq[C_ * C_];
__device__ bf16  g_wk[C_ * C_];
__device__ bf16  g_wv[C_ * C_];

// ---------------------------------------------------------------------------
// helpers (family-safe PTX only: ldmatrix / mma.sync / cp.async)
// ---------------------------------------------------------------------------
__device__ __forceinline__ uint32_t smem_u32(const void* p) {
    return (uint32_t)__cvta_generic_to_shared(p);
}
__device__ __forceinline__ void ldsm4(uint32_t* r, uint32_t addr) {
    asm volatile("ldmatrix.sync.aligned.m8n8.x4.shared.b16 {%0,%1,%2,%3}, [%4];"
                 : "=r"(r[0]), "=r"(r[1]), "=r"(r[2]), "=r"(r[3]) : "r"(addr));
}
__device__ __forceinline__ void mma16816(float* c, const uint32_t* a, const uint32_t* b) {
    asm volatile(
        "mma.sync.aligned.m16n8k16.row.col.f32.bf16.bf16.f32 "
        "{%0,%1,%2,%3}, {%4,%5,%6,%7}, {%8,%9}, {%0,%1,%2,%3};"
        : "+f"(c[0]), "+f"(c[1]), "+f"(c[2]), "+f"(c[3])
        : "r"(a[0]), "r"(a[1]), "r"(a[2]), "r"(a[3]), "r"(b[0]), "r"(b[1]));
}
__device__ __forceinline__ void cp16(uint32_t dst, const void* src) {
    asm volatile("cp.async.cg.shared.global [%0], [%1], 16;" :: "r"(dst), "l"(src));
}
__device__ __forceinline__ void cp_commit() {
    asm volatile("cp.async.commit_group;" ::: "memory");
}
__device__ __forceinline__ void cp_wait1() {
    asm volatile("cp.async.wait_group 1;" ::: "memory");
}
__device__ __forceinline__ void cp_wait0() {
    asm volatile("cp.async.wait_group 0;" ::: "memory");
}

// smem geometry: K_TILE=32 bf16 per row, padded stride 40 (80B -> conflict-free)
#define KT      32
#define STRIDE  40
#define TILE_B  (128 * STRIDE * 2)          // 10240 bytes per operand tile
#define STAGE_B (2 * TILE_B)                // A+B per stage
#define SMEM_B  (2 * STAGE_B)               // 40960 bytes, 2 stages

// ---------------------------------------------------------------------------
// GEMM mainloop: acc[2][8][4] += A[128,K] * B[128,K]^T  (row . col, bf16->fp32)
// A, B row-major with k contiguous. 256 threads, warp grid 4(m) x 2(n).
// ---------------------------------------------------------------------------
__device__ __forceinline__ void copy_tile(const bf16* A, int lda,
                                          const bf16* B, int ldb,
                                          uint32_t sA, uint32_t sB,
                                          int k0, int tid) {
    #pragma unroll
    for (int c = 0; c < 2; c++) {
        int id = tid + 256 * c;             // 512 chunks of 16B per operand
        int row = id >> 2, col = (id & 3) * 8;
        uint32_t off = (uint32_t)(row * STRIDE + col) * 2;
        cp16(sA + off, A + (size_t)row * lda + k0 + col);
        cp16(sB + off, B + (size_t)row * ldb + k0 + col);
    }
    cp_commit();
}

__device__ __forceinline__ void gemm_main(const bf16* A, int lda,
                                          const bf16* B, int ldb, int K,
                                          char* smem, float acc[2][8][4], int tid) {
    int lane = tid & 31, wid = tid >> 5;
    int wm = wid & 3, wn = wid >> 2;
    uint32_t base = smem_u32(smem);
    uint32_t sA0 = base, sB0 = base + TILE_B;
    uint32_t sA1 = base + STAGE_B, sB1 = base + STAGE_B + TILE_B;

    const int T = K / KT;
    copy_tile(A, lda, B, ldb, sA0, sB0, 0, tid);

    int ar = lane & 15, ak = (lane >> 4) * 8;   // ldmatrix lane mapping
    for (int t = 0; t < T; t++) {
        int cur = t & 1;
        if (t + 1 < T) {
            copy_tile(A, lda, B, ldb, (cur ? sA0 : sA1), (cur ? sB0 : sB1),
                      (t + 1) * KT, tid);
            cp_wait1();
        } else {
            cp_wait0();
        }
        __syncthreads();

        uint32_t aB = cur ? sA1 : sA0;   // note: stage t&1 == buffers filled for t
        uint32_t bB = cur ? sB1 : sB0;
        // fix: tile t resides in stage (t&1): stage0 buffers are sA0/sB0
        aB = cur ? sA1 : sA0;
        bB = cur ? sB1 : sB0;

        #pragma unroll
        for (int kk = 0; kk < 2; kk++) {
            uint32_t af[2][4];
            #pragma unroll
            for (int mt = 0; mt < 2; mt++) {
                uint32_t addr = aB + (uint32_t)((wm * 32 + mt * 16 + ar) * STRIDE
                                                + kk * 16 + ak) * 2;
                ldsm4(af[mt], addr);
            }
            uint32_t bfm[8][2];
            #pragma unroll
            for (int np = 0; np < 4; np++) {
                uint32_t r[4];
                uint32_t addr = bB + (uint32_t)((wn * 64 + np * 16 + ar) * STRIDE
                                                + kk * 16 + ak) * 2;
                ldsm4(r, addr);
                bfm[np * 2][0] = r[0];     bfm[np * 2][1] = r[2];
                bfm[np * 2 + 1][0] = r[1]; bfm[np * 2 + 1][1] = r[3];
            }
            #pragma unroll
            for (int mt = 0; mt < 2; mt++)
                #pragma unroll
                for (int nt = 0; nt < 8; nt++)
                    mma16816(acc[mt][nt], af[mt], bfm[nt]);
        }
        __syncthreads();
    }
}

// ---------------------------------------------------------------------------
// 0. weights fp32 -> bf16
// ---------------------------------------------------------------------------
__global__ __launch_bounds__(256) void prep_kernel(const float* __restrict__ Wq,
                                                   const float* __restrict__ Wk,
                                                   const float* __restrict__ Wv) {
    int i = blockIdx.x * 256 + threadIdx.x;
    float4 a; uint2 u; __nv_bfloat162 h0, h1;
    a = reinterpret_cast<const float4*>(Wq)[i];
    h0 = __floats2bfloat162_rn(a.x, a.y); h1 = __floats2bfloat162_rn(a.z, a.w);
    u.x = *reinterpret_cast<uint32_t*>(&h0); u.y = *reinterpret_cast<uint32_t*>(&h1);
    reinterpret_cast<uint2*>(g_wq)[i] = u;
    a = reinterpret_cast<const float4*>(Wk)[i];
    h0 = __floats2bfloat162_rn(a.x, a.y); h1 = __floats2bfloat162_rn(a.z, a.w);
    u.x = *reinterpret_cast<uint32_t*>(&h0); u.y = *reinterpret_cast<uint32_t*>(&h1);
    reinterpret_cast<uint2*>(g_wk)[i] = u;
    a = reinterpret_cast<const float4*>(Wv)[i];
    h0 = __floats2bfloat162_rn(a.x, a.y); h1 = __floats2bfloat162_rn(a.z, a.w);
    u.x = *reinterpret_cast<uint32_t*>(&h0); u.y = *reinterpret_cast<uint32_t*>(&h1);
    reinterpret_cast<uint2*>(g_wv)[i] = u;
}

// ---------------------------------------------------------------------------
// 1. GroupNorm + transpose: x[b][c][n] -> hT[b][n][c] bf16
// ---------------------------------------------------------------------------
__global__ __launch_bounds__(256) void gn_kernel(const float* __restrict__ x,
                                                 const float* __restrict__ gamma,
                                                 const float* __restrict__ beta) {
    int g = blockIdx.x, b = blockIdx.y;
    const float* xp = x + ((size_t)b * C_ + (size_t)g * GC) * N_;
    const int n_el = GC * N_;

    float s = 0.f, ss = 0.f;
    for (int i = threadIdx.x; i < n_el; i += 256) {
        float v = xp[i];
        s += v; ss += v * v;
    }
    __shared__ float sh1[256], sh2[256];
    sh1[threadIdx.x] = s; sh2[threadIdx.x] = ss;
    __syncthreads();
    for (int o = 128; o > 0; o >>= 1) {
        if (threadIdx.x < o) {
            sh1[threadIdx.x] += sh1[threadIdx.x + o];
            sh2[threadIdx.x] += sh2[threadIdx.x + o];
        }
        __syncthreads();
    }
    float mean = sh1[0] * (1.0f / n_el);
    float var  = sh2[0] * (1.0f / n_el) - mean * mean;
    float rstd = rsqrtf(var + 1e-5f);

    __shared__ float tile[32 * 65];
    bf16* out = g_hT + (size_t)b * N_ * C_ + g * GC;
    int tid = threadIdx.x;
    for (int n0 = 0; n0 < N_; n0 += 32) {
        for (int e = tid; e < GC * 32; e += 256) {
            int c = e >> 5, n = e & 31;
            float v = (xp[(size_t)c * N_ + n0 + n] - mean) * rstd;
            v = v * __ldg(&gamma[g * GC + c]) + __ldg(&beta[g * GC + c]);
            tile[n * 65 + c] = v;
        }
        __syncthreads();
        {
            int n = tid >> 3, u = tid & 7;
            uint32_t pk[4];
            #pragma unroll
            for (int j = 0; j < 4; j++) {
                __nv_bfloat162 h = __floats2bfloat162_rn(tile[n * 65 + u * 8 + 2 * j],
                                                         tile[n * 65 + u * 8 + 2 * j + 1]);
                pk[j] = *reinterpret_cast<uint32_t*>(&h);
            }
            *reinterpret_cast<uint4*>(out + (size_t)(n0 + n) * C_ + u * 8) =
                *reinterpret_cast<uint4*>(pk);
        }
        __syncthreads();
    }
}

// ---------------------------------------------------------------------------
// 2. QKV: out = hT @ W^T + b.  mi=0 -> q (x 1/16), mi=1 -> k, mi=2 -> Vt.
// ---------------------------------------------------------------------------
__global__ __launch_bounds__(256) void qkv_kernel(const float* __restrict__ bq,
                                                  const float* __restrict__ bk,
                                                  const float* __restrict__ bv) {
    __shared__ __align__(16) char smem[SMEM_B];
    int tid = threadIdx.x;
    int mi = blockIdx.z % 3, b = blockIdx.z / 3;
    int n0 = blockIdx.x * 128, m0 = blockIdx.y * 128;
    const bf16* A  = g_hT + (size_t)b * N_ * C_ + (size_t)m0 * C_;
    const bf16* Bm = (mi == 0 ? g_wq : mi == 1 ? g_wk : g_wv) + (size_t)n0 * C_;
    float acc[2][8][4] = {};
    gemm_main(A, C_, Bm, C_, C_, smem, acc, tid);

    int lane = tid & 31, wid = tid >> 5;
    int wm = wid & 3, wn = wid >> 2;
    int quad = lane >> 2, qt = lane & 3;
    const float* bias = (mi == 0) ? bq : (mi == 1) ? bk : bv;

    if (mi < 2) {
        bf16* out = ((mi == 0) ? g_q : g_k) + (size_t)b * N_ * C_;
        float scale = (mi == 0) ? 0.0625f : 1.0f;
        #pragma unroll
        for (int mt = 0; mt < 2; mt++) {
            int r0 = m0 + wm * 32 + mt * 16 + quad;
            #pragma unroll
            for (int nt = 0; nt < 8; nt++) {
                int d = n0 + wn * 64 + nt * 8 + qt * 2;
                float b0 = __ldg(&bias[d]), b1 = __ldg(&bias[d + 1]);
                __nv_bfloat162 h0 = __floats2bfloat162_rn((acc[mt][nt][0] + b0) * scale,
                                                          (acc[mt][nt][1] + b1) * scale);
                __nv_bfloat162 h1 = __floats2bfloat162_rn((acc[mt][nt][2] + b0) * scale,
                                                          (acc[mt][nt][3] + b1) * scale);
                *reinterpret_cast<uint32_t*>(out + (size_t)r0 * C_ + d) =
                    *reinterpret_cast<uint32_t*>(&h0);
                *reinterpret_cast<uint32_t*>(out + (size_t)(r0 + 8) * C_ + d) =
                    *reinterpret_cast<uint32_t*>(&h1);
            }
        }
    } else {
        // Vt: stage transposed [d][m] in smem, then coalesced write
        bf16* st = reinterpret_cast<bf16*>(smem);   // stride 136
        __syncthreads();
        #pragma unroll
        for (int mt = 0; mt < 2; mt++) {
            int ml = wm * 32 + mt * 16 + quad;
            #pragma unroll
            for (int nt = 0; nt < 8; nt++) {
                int dl = wn * 64 + nt * 8 + qt * 2;
                float b0 = __ldg(&bias[n0 + dl]), b1 = __ldg(&bias[n0 + dl + 1]);
                st[dl * 136 + ml]           = __float2bfloat16_rn(acc[mt][nt][0] + b0);
                st[(dl + 1) * 136 + ml]     = __float2bfloat16_rn(acc[mt][nt][1] + b1);
                st[dl * 136 + ml + 8]       = __float2bfloat16_rn(acc[mt][nt][2] + b0);
                st[(dl + 1) * 136 + ml + 8] = __float2bfloat16_rn(acc[mt][nt][3] + b1);
            }
        }
        __syncthreads();
        bf16* outv = g_vt + (size_t)b * C_ * N_;
        #pragma unroll
        for (int c = 0; c < 8; c++) {
            int id = tid + 256 * c;          // 2048 chunks of 16B
            int d = id >> 4, ch = (id & 15) * 8;
            *reinterpret_cast<uint4*>(outv + (size_t)(n0 + d) * N_ + m0 + ch) =
                *reinterpret_cast<uint4*>(st + d * 136 + ch);
        }
    }
}

// ---------------------------------------------------------------------------
// 3. Scores: S = Q @ K^T (Q pre-scaled by 1/16), fp32 out
// ---------------------------------------------------------------------------
__global__ __launch_bounds__(256) void score_kernel() {
    __shared__ __align__(16) char smem[SMEM_B];
    int tid = threadIdx.x;
    int b = blockIdx.z;
    int n0 = blockIdx.x * 128, m0 = blockIdx.y * 128;
    const bf16* A  = g_q + (size_t)b * N_ * C_ + (size_t)m0 * C_;
    const bf16* Bm = g_k + (size_t)b * N_ * C_ + (size_t)n0 * C_;
    float acc[2][8][4] = {};
    gemm_main(A, C_, Bm, C_, C_, smem, acc, tid);

    int lane = tid & 31, wid = tid >> 5;
    int wm = wid & 3, wn = wid >> 2;
    int quad = lane >> 2, qt = lane & 3;
    float* S = g_s + (size_t)b * N_ * N_;
    #pragma unroll
    for (int mt = 0; mt < 2; mt++) {
        int r0 = m0 + wm * 32 + mt * 16 + quad;
        #pragma unroll
        for (int nt = 0; nt < 8; nt++) {
            int cc = n0 + wn * 64 + nt * 8 + qt * 2;
            float2 lo = make_float2(acc[mt][nt][0], acc[mt][nt][1]);
            float2 hi = make_float2(acc[mt][nt][2], acc[mt][nt][3]);
            *reinterpret_cast<float2*>(S + (size_t)r0 * N_ + cc) = lo;
            *reinterpret_cast<float2*>(S + (size_t)(r0 + 8) * N_ + cc) = hi;
        }
    }
}

// ---------------------------------------------------------------------------
// 4. Softmax (fp32 in, bf16 out)
// ---------------------------------------------------------------------------
__global__ __launch_bounds__(256) void softmax_kernel() {
    size_t row = blockIdx.x;
    const float* S = g_s + row * N_;
    bf16* P = g_p + row * N_;
    int t = threadIdx.x;

    float vals[4];
    float lm = -1e30f;
    #pragma unroll
    for (int i = 0; i < 4; i++) {
        vals[i] = S[t + i * 256];
        lm = fmaxf(lm, vals[i]);
    }
    __shared__ float sh[256];
    sh[t] = lm;
    __syncthreads();
    for (int o = 128; o > 0; o >>= 1) {
        if (t < o) sh[t] = fmaxf(sh[t], sh[t + o]);
        __syncthreads();
    }
    float m = sh[0];
    __syncthreads();

    float s = 0.f;
    #pragma unroll
    for (int i = 0; i < 4; i++) {
        vals[i] = __expf(vals[i] - m);
        s += vals[i];
    }
    sh[t] = s;
    __syncthreads();
    for (int o = 128; o > 0; o >>= 1) {
        if (t < o) sh[t] += sh[t + o];
        __syncthreads();
    }
    float inv = 1.0f / sh[0];
    #pragma unroll
    for (int i = 0; i < 4; i++) P[t + i * 256] = __float2bfloat16_rn(vals[i] * inv);
}

// ---------------------------------------------------------------------------
// 5. PV as O^T: out[b][c][n] = sum_m Vt[b][c][m] * P[b][n][m] + x[b][c][n]
// ---------------------------------------------------------------------------
__global__ __launch_bounds__(256) void pv_kernel(const float* __restrict__ x,
                                                 float* __restrict__ outp) {
    __shared__ __align__(16) char smem[SMEM_B];
    int tid = threadIdx.x;
    int b = blockIdx.z;
    int n0 = blockIdx.x * 128;   // token tile
    int m0 = blockIdx.y * 128;   // channel tile
    const bf16* A  = g_vt + (size_t)b * C_ * N_ + (size_t)m0 * N_;
    const bf16* Bm = g_p  + (size_t)b * N_ * N_ + (size_t)n0 * N_;
    float acc[2][8][4] = {};
    gemm_main(A, N_, Bm, N_, N_, smem, acc, tid);

    int lane = tid & 31, wid = tid >> 5;
    int wm = wid & 3, wn = wid >> 2;
    int quad = lane >> 2, qt = lane & 3;
    #pragma unroll
    for (int mt = 0; mt < 2; mt++) {
        int cg = m0 + wm * 32 + mt * 16 + quad;   // channel
        #pragma unroll
        for (int nt = 0; nt < 8; nt++) {
            int ng = n0 + wn * 64 + nt * 8 + qt * 2;  // token
            size_t base = ((size_t)b * C_ + cg) * N_ + ng;
            float2 xv = *reinterpret_cast<const float2*>(x + base);
            float2 o  = make_float2(acc[mt][nt][0] + xv.x, acc[mt][nt][1] + xv.y);
            *reinterpret_cast<float2*>(outp + base) = o;
            size_t base8 = base + (size_t)8 * N_;
            float2 xv8 = *reinterpret_cast<const float2*>(x + base8);
            float2 o8  = make_float2(acc[mt][nt][2] + xv8.x, acc[mt][nt][3] + xv8.y);
            *reinterpret_cast<float2*>(outp + base8) = o8;
        }
    }
}

// ---------------------------------------------------------------------------
extern "C" void kernel_launch(void* const* d_in, const int* in_sizes, int n_in,
                              void* d_out, int out_size) {
    const float* x     = (const float*)d_in[0];
    const float* Wq    = (const float*)d_in[1];
    const float* bq    = (const float*)d_in[2];
    const float* Wk    = (const float*)d_in[3];
    const float* bk    = (const float*)d_in[4];
    const float* Wv    = (const float*)d_in[5];
    const float* bv    = (const float*)d_in[6];
    const float* gamma = (const float*)d_in[7];
    const float* beta  = (const float*)d_in[8];
    float* out = (float*)d_out;

    prep_kernel<<<64, 256>>>(Wq, Wk, Wv);
    gn_kernel<<<dim3(NG, B_), 256>>>(x, gamma, beta);
    qkv_kernel<<<dim3(2, 8, 3 * B_), 256>>>(bq, bk, bv);
    score_kernel<<<dim3(8, 8, B_), 256>>>();
    softmax_kernel<<<B_ * N_, 256>>>();
    pv_kernel<<<dim3(8, 2, B_), 256>>>(x, out);
}

// round 4
// speedup vs baseline: 4.3167x; 1.2171x over previous
#include <cuda_runtime.h>
#include <cuda_bf16.h>
#include <cstdint>

#define B_  16
#define C_  256
#define N_  1024
#define NG  4
#define GC  64

typedef __nv_bfloat16 bf16;

// ---- scratch (static device globals) ----
__device__ bf16  g_hT[(size_t)B_ * N_ * C_];   // groupnorm out, [b][n][c]
__device__ bf16  g_q [(size_t)B_ * N_ * C_];   // [b][n][d], pre-scaled by 1/16
__device__ bf16  g_k [(size_t)B_ * N_ * C_];
__device__ bf16  g_vt[(size_t)B_ * C_ * N_];   // V transposed: [b][d][m]
__device__ bf16  g_p [(size_t)B_ * N_ * N_];   // probs bf16 [query][key]
__device__ bf16  g_wq[C_ * C_];
__device__ bf16  g_wk[C_ * C_];
__device__ bf16  g_wv[C_ * C_];
__device__ float g_red[B_ * NG][8][2];         // groupnorm partial sums

// ---------------------------------------------------------------------------
// helpers (family-safe PTX: ldmatrix / mma.sync / cp.async)
// ---------------------------------------------------------------------------
__device__ __forceinline__ uint32_t smem_u32(const void* p) {
    return (uint32_t)__cvta_generic_to_shared(p);
}
__device__ __forceinline__ void ldsm4(uint32_t* r, uint32_t addr) {
    asm volatile("ldmatrix.sync.aligned.m8n8.x4.shared.b16 {%0,%1,%2,%3}, [%4];"
                 : "=r"(r[0]), "=r"(r[1]), "=r"(r[2]), "=r"(r[3]) : "r"(addr));
}
__device__ __forceinline__ void mma16816(float* c, const uint32_t* a, const uint32_t* b) {
    asm volatile(
        "mma.sync.aligned.m16n8k16.row.col.f32.bf16.bf16.f32 "
        "{%0,%1,%2,%3}, {%4,%5,%6,%7}, {%8,%9}, {%0,%1,%2,%3};"
        : "+f"(c[0]), "+f"(c[1]), "+f"(c[2]), "+f"(c[3])
        : "r"(a[0]), "r"(a[1]), "r"(a[2]), "r"(a[3]), "r"(b[0]), "r"(b[1]));
}
__device__ __forceinline__ void cp16(uint32_t dst, const void* src) {
    asm volatile("cp.async.cg.shared.global [%0], [%1], 16;" :: "r"(dst), "l"(src));
}
__device__ __forceinline__ void cp_commit() { asm volatile("cp.async.commit_group;" ::: "memory"); }
__device__ __forceinline__ void cp_wait1()  { asm volatile("cp.async.wait_group 1;" ::: "memory"); }
__device__ __forceinline__ void cp_wait0()  { asm volatile("cp.async.wait_group 0;" ::: "memory"); }

#define KT      32
#define STRIDE  40
#define TILE_B  (128 * STRIDE * 2)
#define STAGE_B (2 * TILE_B)
#define SMEM_B  (2 * STAGE_B)

// ---------------------------------------------------------------------------
// Generic 128x128 GEMM mainloop (as R3): acc += A[128,K] * B[128,K]^T
// ---------------------------------------------------------------------------
__device__ __forceinline__ void copy_tile(const bf16* A, int lda, const bf16* B, int ldb,
                                          uint32_t sA, uint32_t sB, int k0, int tid) {
    #pragma unroll
    for (int c = 0; c < 2; c++) {
        int id = tid + 256 * c;
        int row = id >> 2, col = (id & 3) * 8;
        uint32_t off = (uint32_t)(row * STRIDE + col) * 2;
        cp16(sA + off, A + (size_t)row * lda + k0 + col);
        cp16(sB + off, B + (size_t)row * ldb + k0 + col);
    }
    cp_commit();
}

__device__ __forceinline__ void gemm_main(const bf16* A, int lda, const bf16* B, int ldb,
                                          int K, char* smem, float acc[2][8][4], int tid) {
    int lane = tid & 31, wid = tid >> 5;
    int wm = wid & 3, wn = wid >> 2;
    uint32_t base = smem_u32(smem);
    uint32_t sA0 = base, sB0 = base + TILE_B;
    uint32_t sA1 = base + STAGE_B, sB1 = base + STAGE_B + TILE_B;

    const int T = K / KT;
    copy_tile(A, lda, B, ldb, sA0, sB0, 0, tid);

    int ar = lane & 15, ak = (lane >> 4) * 8;
    for (int t = 0; t < T; t++) {
        int cur = t & 1;
        if (t + 1 < T) {
            copy_tile(A, lda, B, ldb, (cur ? sA0 : sA1), (cur ? sB0 : sB1), (t + 1) * KT, tid);
            cp_wait1();
        } else {
            cp_wait0();
        }
        __syncthreads();
        uint32_t aB = cur ? sA1 : sA0;
        uint32_t bB = cur ? sB1 : sB0;

        #pragma unroll
        for (int kk = 0; kk < 2; kk++) {
            uint32_t af[2][4];
            #pragma unroll
            for (int mt = 0; mt < 2; mt++)
                ldsm4(af[mt], aB + (uint32_t)((wm * 32 + mt * 16 + ar) * STRIDE + kk * 16 + ak) * 2);
            uint32_t bfm[8][2];
            #pragma unroll
            for (int np = 0; np < 4; np++) {
                uint32_t r[4];
                ldsm4(r, bB + (uint32_t)((wn * 64 + np * 16 + ar) * STRIDE + kk * 16 + ak) * 2);
                bfm[np * 2][0] = r[0];     bfm[np * 2][1] = r[2];
                bfm[np * 2 + 1][0] = r[1]; bfm[np * 2 + 1][1] = r[3];
            }
            #pragma unroll
            for (int mt = 0; mt < 2; mt++)
                #pragma unroll
                for (int nt = 0; nt < 8; nt++)
                    mma16816(acc[mt][nt], af[mt], bfm[nt]);
        }
        __syncthreads();
    }
}

// ---------------------------------------------------------------------------
// 0. weights fp32 -> bf16
// ---------------------------------------------------------------------------
__global__ __launch_bounds__(256) void prep_kernel(const float* __restrict__ Wq,
                                                   const float* __restrict__ Wk,
                                                   const float* __restrict__ Wv) {
    int i = blockIdx.x * 256 + threadIdx.x;
    float4 a; uint2 u; __nv_bfloat162 h0, h1;
    a = reinterpret_cast<const float4*>(Wq)[i];
    h0 = __floats2bfloat162_rn(a.x, a.y); h1 = __floats2bfloat162_rn(a.z, a.w);
    u.x = *reinterpret_cast<uint32_t*>(&h0); u.y = *reinterpret_cast<uint32_t*>(&h1);
    reinterpret_cast<uint2*>(g_wq)[i] = u;
    a = reinterpret_cast<const float4*>(Wk)[i];
    h0 = __floats2bfloat162_rn(a.x, a.y); h1 = __floats2bfloat162_rn(a.z, a.w);
    u.x = *reinterpret_cast<uint32_t*>(&h0); u.y = *reinterpret_cast<uint32_t*>(&h1);
    reinterpret_cast<uint2*>(g_wk)[i] = u;
    a = reinterpret_cast<const float4*>(Wv)[i];
    h0 = __floats2bfloat162_rn(a.x, a.y); h1 = __floats2bfloat162_rn(a.z, a.w);
    u.x = *reinterpret_cast<uint32_t*>(&h0); u.y = *reinterpret_cast<uint32_t*>(&h1);
    reinterpret_cast<uint2*>(g_wv)[i] = u;
}

// ---------------------------------------------------------------------------
// 1a. GroupNorm stats: partial sum/sumsq per (b,g) slice
// ---------------------------------------------------------------------------
__global__ __launch_bounds__(256) void gn_stats_kernel(const float* __restrict__ x) {
    int s = blockIdx.x, bg = blockIdx.y;
    const float* xp = x + (size_t)bg * GC * N_ + (size_t)s * 8192;
    float sum = 0.f, ss = 0.f;
    #pragma unroll
    for (int i = 0; i < 8; i++) {
        float4 v = reinterpret_cast<const float4*>(xp)[threadIdx.x + i * 256];
        sum += v.x + v.y + v.z + v.w;
        ss  += v.x * v.x + v.y * v.y + v.z * v.z + v.w * v.w;
    }
    __shared__ float sh1[256], sh2[256];
    sh1[threadIdx.x] = sum; sh2[threadIdx.x] = ss;
    __syncthreads();
    for (int o = 128; o > 0; o >>= 1) {
        if (threadIdx.x < o) {
            sh1[threadIdx.x] += sh1[threadIdx.x + o];
            sh2[threadIdx.x] += sh2[threadIdx.x + o];
        }
        __syncthreads();
    }
    if (threadIdx.x == 0) {
        g_red[bg][s][0] = sh1[0];
        g_red[bg][s][1] = sh2[0];
    }
}

// ---------------------------------------------------------------------------
// 1b. GroupNorm apply + transpose: x[b][c][n] -> hT[b][n][c] bf16
// ---------------------------------------------------------------------------
__global__ __launch_bounds__(256) void gn_apply_kernel(const float* __restrict__ x,
                                                       const float* __restrict__ gamma,
                                                       const float* __restrict__ beta) {
    int ns = blockIdx.x, g = blockIdx.y, b = blockIdx.z;
    int bg = b * NG + g;
    float sum = 0.f, ss = 0.f;
    #pragma unroll
    for (int i = 0; i < 8; i++) { sum += g_red[bg][i][0]; ss += g_red[bg][i][1]; }
    const float inv_n = 1.0f / (GC * N_);
    float mean = sum * inv_n;
    float var  = ss * inv_n - mean * mean;
    float rstd = rsqrtf(var + 1e-5f);

    const float* xp = x + (size_t)bg * GC * N_;
    bf16* out = g_hT + (size_t)b * N_ * C_ + g * GC;
    __shared__ float tile[32 * 65];
    int tid = threadIdx.x;
    int nbase = ns * 128;
    for (int n0 = nbase; n0 < nbase + 128; n0 += 32) {
        for (int e = tid; e < GC * 32; e += 256) {
            int c = e >> 5, n = e & 31;
            float v = (xp[(size_t)c * N_ + n0 + n] - mean) * rstd;
            v = v * __ldg(&gamma[g * GC + c]) + __ldg(&beta[g * GC + c]);
            tile[n * 65 + c] = v;
        }
        __syncthreads();
        {
            int n = tid >> 3, u = tid & 7;
            uint32_t pk[4];
            #pragma unroll
            for (int j = 0; j < 4; j++) {
                __nv_bfloat162 h = __floats2bfloat162_rn(tile[n * 65 + u * 8 + 2 * j],
                                                         tile[n * 65 + u * 8 + 2 * j + 1]);
                pk[j] = *reinterpret_cast<uint32_t*>(&h);
            }
            *reinterpret_cast<uint4*>(out + (size_t)(n0 + n) * C_ + u * 8) =
                *reinterpret_cast<uint4*>(pk);
        }
        __syncthreads();
    }
}

// ---------------------------------------------------------------------------
// 2. QKV: out = hT @ W^T + b.  mi=0 -> q (x 1/16), mi=1 -> k, mi=2 -> Vt.
// ---------------------------------------------------------------------------
__global__ __launch_bounds__(256) void qkv_kernel(const float* __restrict__ bq,
                                                  const float* __restrict__ bk,
                                                  const float* __restrict__ bv) {
    __shared__ __align__(16) char smem[SMEM_B];
    int tid = threadIdx.x;
    int mi = blockIdx.z % 3, b = blockIdx.z / 3;
    int n0 = blockIdx.x * 128, m0 = blockIdx.y * 128;
    const bf16* A  = g_hT + (size_t)b * N_ * C_ + (size_t)m0 * C_;
    const bf16* Bm = (mi == 0 ? g_wq : mi == 1 ? g_wk : g_wv) + (size_t)n0 * C_;
    float acc[2][8][4] = {};
    gemm_main(A, C_, Bm, C_, C_, smem, acc, tid);

    int lane = tid & 31, wid = tid >> 5;
    int wm = wid & 3, wn = wid >> 2;
    int quad = lane >> 2, qt = lane & 3;
    const float* bias = (mi == 0) ? bq : (mi == 1) ? bk : bv;

    if (mi < 2) {
        bf16* out = ((mi == 0) ? g_q : g_k) + (size_t)b * N_ * C_;
        float scale = (mi == 0) ? 0.0625f : 1.0f;
        #pragma unroll
        for (int mt = 0; mt < 2; mt++) {
            int r0 = m0 + wm * 32 + mt * 16 + quad;
            #pragma unroll
            for (int nt = 0; nt < 8; nt++) {
                int d = n0 + wn * 64 + nt * 8 + qt * 2;
                float b0 = __ldg(&bias[d]), b1 = __ldg(&bias[d + 1]);
                __nv_bfloat162 h0 = __floats2bfloat162_rn((acc[mt][nt][0] + b0) * scale,
                                                          (acc[mt][nt][1] + b1) * scale);
                __nv_bfloat162 h1 = __floats2bfloat162_rn((acc[mt][nt][2] + b0) * scale,
                                                          (acc[mt][nt][3] + b1) * scale);
                *reinterpret_cast<uint32_t*>(out + (size_t)r0 * C_ + d) =
                    *reinterpret_cast<uint32_t*>(&h0);
                *reinterpret_cast<uint32_t*>(out + (size_t)(r0 + 8) * C_ + d) =
                    *reinterpret_cast<uint32_t*>(&h1);
            }
        }
    } else {
        bf16* st = reinterpret_cast<bf16*>(smem);   // stride 136
        __syncthreads();
        #pragma unroll
        for (int mt = 0; mt < 2; mt++) {
            int ml = wm * 32 + mt * 16 + quad;
            #pragma unroll
            for (int nt = 0; nt < 8; nt++) {
                int dl = wn * 64 + nt * 8 + qt * 2;
                float b0 = __ldg(&bias[n0 + dl]), b1 = __ldg(&bias[n0 + dl + 1]);
                st[dl * 136 + ml]           = __float2bfloat16_rn(acc[mt][nt][0] + b0);
                st[(dl + 1) * 136 + ml]     = __float2bfloat16_rn(acc[mt][nt][1] + b1);
                st[dl * 136 + ml + 8]       = __float2bfloat16_rn(acc[mt][nt][2] + b0);
                st[(dl + 1) * 136 + ml + 8] = __float2bfloat16_rn(acc[mt][nt][3] + b1);
            }
        }
        __syncthreads();
        bf16* outv = g_vt + (size_t)b * C_ * N_;
        #pragma unroll
        for (int c = 0; c < 8; c++) {
            int id = tid + 256 * c;
            int d = id >> 4, ch = (id & 15) * 8;
            *reinterpret_cast<uint4*>(outv + (size_t)(n0 + d) * N_ + m0 + ch) =
                *reinterpret_cast<uint4*>(st + d * 136 + ch);
        }
    }
}

// ---------------------------------------------------------------------------
// 3. FUSED scores+softmax: P[b][m0+0:32][0:1024] = softmax(Q K^T)
//    CTA: 32 query rows, full 1024 keys in registers. 8 warps, each a 128-key
//    slice. K-loop over channels (KT=32), double-buffered cp.async, dynamic smem.
// ---------------------------------------------------------------------------
#define FS_STAGE ((1024 + 32) * STRIDE * 2)   // K tile + Q tile, bytes
#define FS_SMEM  (2 * FS_STAGE)

__device__ __forceinline__ void fs_copy(const bf16* Q, const bf16* K,
                                        uint32_t sK, uint32_t sQ, int k0, int tid) {
    #pragma unroll
    for (int i = 0; i < 17; i++) {
        int id = tid + 256 * i;
        if (id < 4096) {
            int row = id >> 2, col = (id & 3) * 8;
            cp16(sK + (uint32_t)(row * STRIDE + col) * 2, K + (size_t)row * C_ + k0 + col);
        } else if (id < 4224) {
            int q = id - 4096;
            int row = q >> 2, col = (q & 3) * 8;
            cp16(sQ + (uint32_t)(row * STRIDE + col) * 2, Q + (size_t)row * C_ + k0 + col);
        }
    }
    cp_commit();
}

__global__ __launch_bounds__(256, 1) void score_softmax_kernel() {
    extern __shared__ __align__(16) char dsm[];
    int tid = threadIdx.x;
    int lane = tid & 31, wid = tid >> 5;
    int quad = lane >> 2, qt = lane & 3;
    int b = blockIdx.y, m0 = blockIdx.x * 32;

    const bf16* Q = g_q + (size_t)b * N_ * C_ + (size_t)m0 * C_;
    const bf16* K = g_k + (size_t)b * N_ * C_;

    uint32_t base = smem_u32(dsm);
    uint32_t sK0 = base, sQ0 = base + 1024 * STRIDE * 2;
    uint32_t sK1 = base + FS_STAGE, sQ1 = sK1 + 1024 * STRIDE * 2;

    float acc[2][16][4] = {};   // [mt][nt][e]; warp n-slice = wid*128

    fs_copy(Q, K, sK0, sQ0, 0, tid);
    int ar = lane & 15, ak = (lane >> 4) * 8;
    const int T = C_ / KT;  // 8
    for (int t = 0; t < T; t++) {
        int cur = t & 1;
        if (t + 1 < T) {
            fs_copy(Q, K, cur ? sK0 : sK1, cur ? sQ0 : sQ1, (t + 1) * KT, tid);
            cp_wait1();
        } else {
            cp_wait0();
        }
        __syncthreads();
        uint32_t kB = cur ? sK1 : sK0;
        uint32_t qB = cur ? sQ1 : sQ0;

        #pragma unroll
        for (int kk = 0; kk < 2; kk++) {
            uint32_t af[2][4];
            #pragma unroll
            for (int mt = 0; mt < 2; mt++)
                ldsm4(af[mt], qB + (uint32_t)((mt * 16 + ar) * STRIDE + kk * 16 + ak) * 2);
            #pragma unroll
            for (int np = 0; np < 8; np++) {
                uint32_t r[4];
                ldsm4(r, kB + (uint32_t)((wid * 128 + np * 16 + ar) * STRIDE + kk * 16 + ak) * 2);
                uint32_t b0[2] = {r[0], r[2]};
                uint32_t b1[2] = {r[1], r[3]};
                #pragma unroll
                for (int mt = 0; mt < 2; mt++) {
                    mma16816(acc[mt][np * 2],     af[mt], b0);
                    mma16816(acc[mt][np * 2 + 1], af[mt], b1);
                }
            }
        }
        __syncthreads();
    }

    // ---- softmax over full rows (keys dim distributed over 8 warps) ----
    float* red = reinterpret_cast<float*>(dsm);          // [32][8]
    float* red2 = red + 32 * 8;                          // [32][8]

    // 1. row max: thread-local over nt, shuffle over quad lanes
    float rmax[2][2];
    #pragma unroll
    for (int mt = 0; mt < 2; mt++) {
        float m0v = -1e30f, m1v = -1e30f;
        #pragma unroll
        for (int nt = 0; nt < 16; nt++) {
            m0v = fmaxf(m0v, fmaxf(acc[mt][nt][0], acc[mt][nt][1]));
            m1v = fmaxf(m1v, fmaxf(acc[mt][nt][2], acc[mt][nt][3]));
        }
        m0v = fmaxf(m0v, __shfl_xor_sync(0xffffffffu, m0v, 1));
        m0v = fmaxf(m0v, __shfl_xor_sync(0xffffffffu, m0v, 2));
        m1v = fmaxf(m1v, __shfl_xor_sync(0xffffffffu, m1v, 1));
        m1v = fmaxf(m1v, __shfl_xor_sync(0xffffffffu, m1v, 2));
        rmax[mt][0] = m0v; rmax[mt][1] = m1v;
    }
    if (qt == 0) {
        #pragma unroll
        for (int mt = 0; mt < 2; mt++) {
            red[(mt * 16 + quad) * 8 + wid]     = rmax[mt][0];
            red[(mt * 16 + 8 + quad) * 8 + wid] = rmax[mt][1];
        }
    }
    __syncthreads();
    float M[2][2];
    #pragma unroll
    for (int mt = 0; mt < 2; mt++)
        #pragma unroll
        for (int h = 0; h < 2; h++) {
            float m = -1e30f;
            #pragma unroll
            for (int w8 = 0; w8 < 8; w8++) m = fmaxf(m, red[(mt * 16 + h * 8 + quad) * 8 + w8]);
            M[mt][h] = m;
        }

    // 2. exp + row sum
    float rsum[2][2] = {{0.f, 0.f}, {0.f, 0.f}};
    #pragma unroll
    for (int mt = 0; mt < 2; mt++)
        #pragma unroll
        for (int nt = 0; nt < 16; nt++) {
            acc[mt][nt][0] = __expf(acc[mt][nt][0] - M[mt][0]);
            acc[mt][nt][1] = __expf(acc[mt][nt][1] - M[mt][0]);
            acc[mt][nt][2] = __expf(acc[mt][nt][2] - M[mt][1]);
            acc[mt][nt][3] = __expf(acc[mt][nt][3] - M[mt][1]);
            rsum[mt][0] += acc[mt][nt][0] + acc[mt][nt][1];
            rsum[mt][1] += acc[mt][nt][2] + acc[mt][nt][3];
        }
    #pragma unroll
    for (int mt = 0; mt < 2; mt++)
        #pragma unroll
        for (int h = 0; h < 2; h++) {
            float s = rsum[mt][h];
            s += __shfl_xor_sync(0xffffffffu, s, 1);
            s += __shfl_xor_sync(0xffffffffu, s, 2);
            rsum[mt][h] = s;
        }
    if (qt == 0) {
        #pragma unroll
        for (int mt = 0; mt < 2; mt++) {
            red2[(mt * 16 + quad) * 8 + wid]     = rsum[mt][0];
            red2[(mt * 16 + 8 + quad) * 8 + wid] = rsum[mt][1];
        }
    }
    __syncthreads();
    float inv[2][2];
    #pragma unroll
    for (int mt = 0; mt < 2; mt++)
        #pragma unroll
        for (int h = 0; h < 2; h++) {
            float s = 0.f;
            #pragma unroll
            for (int w8 = 0; w8 < 8; w8++) s += red2[(mt * 16 + h * 8 + quad) * 8 + w8];
            inv[mt][h] = 1.0f / s;
        }

    // 3. write P bf16
    bf16* P = g_p + (size_t)b * N_ * N_;
    #pragma unroll
    for (int mt = 0; mt < 2; mt++) {
        int r0 = m0 + mt * 16 + quad;
        #pragma unroll
        for (int nt = 0; nt < 16; nt++) {
            int cc = wid * 128 + nt * 8 + qt * 2;
            __nv_bfloat162 h0 = __floats2bfloat162_rn(acc[mt][nt][0] * inv[mt][0],
                                                      acc[mt][nt][1] * inv[mt][0]);
            __nv_bfloat162 h1 = __floats2bfloat162_rn(acc[mt][nt][2] * inv[mt][1],
                                                      acc[mt][nt][3] * inv[mt][1]);
            *reinterpret_cast<uint32_t*>(P + (size_t)r0 * N_ + cc) =
                *reinterpret_cast<uint32_t*>(&h0);
            *reinterpret_cast<uint32_t*>(P + (size_t)(r0 + 8) * N_ + cc) =
                *reinterpret_cast<uint32_t*>(&h1);
        }
    }
}

// ---------------------------------------------------------------------------
// 5. PV as O^T: out[b][c][n] = sum_m Vt[b][c][m] * P[b][n][m] + x[b][c][n]
// ---------------------------------------------------------------------------
__global__ __launch_bounds__(256) void pv_kernel(const float* __restrict__ x,
                                                 float* __restrict__ outp) {
    __shared__ __align__(16) char smem[SMEM_B];
    int tid = threadIdx.x;
    int b = blockIdx.z;
    int n0 = blockIdx.x * 128;   // token tile
    int m0 = blockIdx.y * 128;   // channel tile
    const bf16* A  = g_vt + (size_t)b * C_ * N_ + (size_t)m0 * N_;
    const bf16* Bm = g_p  + (size_t)b * N_ * N_ + (size_t)n0 * N_;
    float acc[2][8][4] = {};
    gemm_main(A, N_, Bm, N_, N_, smem, acc, tid);

    int lane = tid & 31, wid = tid >> 5;
    int wm = wid & 3, wn = wid >> 2;
    int quad = lane >> 2, qt = lane & 3;
    #pragma unroll
    for (int mt = 0; mt < 2; mt++) {
        int cg = m0 + wm * 32 + mt * 16 + quad;
        #pragma unroll
        for (int nt = 0; nt < 8; nt++) {
            int ng = n0 + wn * 64 + nt * 8 + qt * 2;
            size_t base = ((size_t)b * C_ + cg) * N_ + ng;
            float2 xv = *reinterpret_cast<const float2*>(x + base);
            *reinterpret_cast<float2*>(outp + base) =
                make_float2(acc[mt][nt][0] + xv.x, acc[mt][nt][1] + xv.y);
            size_t base8 = base + (size_t)8 * N_;
            float2 xv8 = *reinterpret_cast<const float2*>(x + base8);
            *reinterpret_cast<float2*>(outp + base8) =
                make_float2(acc[mt][nt][2] + xv8.x, acc[mt][nt][3] + xv8.y);
        }
    }
}

// ---------------------------------------------------------------------------
extern "C" void kernel_launch(void* const* d_in, const int* in_sizes, int n_in,
                              void* d_out, int out_size) {
    const float* x     = (const float*)d_in[0];
    const float* Wq    = (const float*)d_in[1];
    const float* bq    = (const float*)d_in[2];
    const float* Wk    = (const float*)d_in[3];
    const float* bk    = (const float*)d_in[4];
    const float* Wv    = (const float*)d_in[5];
    const float* bv    = (const float*)d_in[6];
    const float* gamma = (const float*)d_in[7];
    const float* beta  = (const float*)d_in[8];
    float* out = (float*)d_out;

    static bool attr_set = false;
    if (!attr_set) {
        cudaFuncSetAttribute(score_softmax_kernel,
                             cudaFuncAttributeMaxDynamicSharedMemorySize, FS_SMEM);
        attr_set = true;
    }

    prep_kernel<<<64, 256>>>(Wq, Wk, Wv);
    gn_stats_kernel<<<dim3(8, B_ * NG), 256>>>(x);
    gn_apply_kernel<<<dim3(8, NG, B_), 256>>>(x, gamma, beta);
    qkv_kernel<<<dim3(2, 8, 3 * B_), 256>>>(bq, bk, bv);
    score_softmax_kernel<<<dim3(32, B_), 256, FS_SMEM>>>();
    pv_kernel<<<dim3(8, 2, B_), 256>>>(x, out);
}

// round 5
// speedup vs baseline: 4.3667x; 1.0116x over previous
#include <cuda_runtime.h>
#include <cuda_bf16.h>
#include <cstdint>

#define B_  16
#define C_  256
#define N_  1024
#define NG  4
#define GC  64

typedef __nv_bfloat16 bf16;

// ---- scratch (static device globals) ----
__device__ bf16  g_hT[(size_t)B_ * N_ * C_];   // groupnorm out, [b][n][c]
__device__ bf16  g_q [(size_t)B_ * N_ * C_];   // [b][n][d], pre-scaled by 1/16
__device__ bf16  g_k [(size_t)B_ * N_ * C_];
__device__ bf16  g_vt[(size_t)B_ * C_ * N_];   // V transposed: [b][d][m]
__device__ bf16  g_p [(size_t)B_ * N_ * N_];   // probs bf16 [query][key]
__device__ bf16  g_wq[C_ * C_];
__device__ bf16  g_wk[C_ * C_];
__device__ bf16  g_wv[C_ * C_];
__device__ float g_red[B_ * NG][8][2];         // groupnorm partial sums

// ---------------------------------------------------------------------------
// helpers (family-safe PTX: ldmatrix / mma.sync / cp.async)
// ---------------------------------------------------------------------------
__device__ __forceinline__ uint32_t smem_u32(const void* p) {
    return (uint32_t)__cvta_generic_to_shared(p);
}
__device__ __forceinline__ void ldsm4(uint32_t* r, uint32_t addr) {
    asm volatile("ldmatrix.sync.aligned.m8n8.x4.shared.b16 {%0,%1,%2,%3}, [%4];"
                 : "=r"(r[0]), "=r"(r[1]), "=r"(r[2]), "=r"(r[3]) : "r"(addr));
}
__device__ __forceinline__ void mma16816(float* c, const uint32_t* a, const uint32_t* b) {
    asm volatile(
        "mma.sync.aligned.m16n8k16.row.col.f32.bf16.bf16.f32 "
        "{%0,%1,%2,%3}, {%4,%5,%6,%7}, {%8,%9}, {%0,%1,%2,%3};"
        : "+f"(c[0]), "+f"(c[1]), "+f"(c[2]), "+f"(c[3])
        : "r"(a[0]), "r"(a[1]), "r"(a[2]), "r"(a[3]), "r"(b[0]), "r"(b[1]));
}
__device__ __forceinline__ void cp16(uint32_t dst, const void* src) {
    asm volatile("cp.async.cg.shared.global [%0], [%1], 16;" :: "r"(dst), "l"(src));
}
__device__ __forceinline__ void cp_commit() { asm volatile("cp.async.commit_group;" ::: "memory"); }
__device__ __forceinline__ void cp_wait0()  { asm volatile("cp.async.wait_group 0;" ::: "memory"); }
__device__ __forceinline__ void cp_wait2()  { asm volatile("cp.async.wait_group 2;" ::: "memory"); }

#define KT      32
#define STRIDE  40
#define TILE_B  (128 * STRIDE * 2)      // 10240 B per operand tile
#define STG_B   (2 * TILE_B)            // 20480 B per stage (A+B)
#define NSTAGE  4
#define GEMM_SMEM (NSTAGE * STG_B)      // 81920 B

// ---------------------------------------------------------------------------
// Multistage 128x128 GEMM: acc += A[128,K] * B[128,K]^T (bf16 -> fp32)
// 256 threads, warp grid 4(m) x 2(n), 4-stage cp.async pipeline, 1 sync/tile.
// ---------------------------------------------------------------------------
__device__ __forceinline__ void copy_tile(const bf16* A, int lda, const bf16* B, int ldb,
                                          uint32_t sA, uint32_t sB, int k0, int tid) {
    #pragma unroll
    for (int c = 0; c < 2; c++) {
        int id = tid + 256 * c;
        int row = id >> 2, col = (id & 3) * 8;
        uint32_t off = (uint32_t)(row * STRIDE + col) * 2;
        cp16(sA + off, A + (size_t)row * lda + k0 + col);
        cp16(sB + off, B + (size_t)row * ldb + k0 + col);
    }
    cp_commit();
}

__device__ __forceinline__ void gemm_ms(const bf16* A, int lda, const bf16* B, int ldb,
                                        int T, char* smem, float acc[2][8][4], int tid) {
    int lane = tid & 31, wid = tid >> 5;
    int wm = wid & 3, wn = wid >> 2;
    uint32_t base = smem_u32(smem);

    #pragma unroll
    for (int s = 0; s < NSTAGE - 1; s++)
        copy_tile(A, lda, B, ldb, base + s * STG_B, base + s * STG_B + TILE_B, s * KT, tid);

    int ar = lane & 15, ak = (lane >> 4) * 8;
    for (int t = 0; t < T; t++) {
        cp_wait2();              // tile t resident (<=2 younger groups pending)
        __syncthreads();         // visibility + guards reuse of buf (t-1)%4
        int nxt = t + NSTAGE - 1;
        if (nxt < T) {
            uint32_t sb = base + (nxt % NSTAGE) * STG_B;
            copy_tile(A, lda, B, ldb, sb, sb + TILE_B, nxt * KT, tid);
        } else {
            cp_commit();         // keep group accounting uniform
        }
        uint32_t aB = base + (t % NSTAGE) * STG_B;
        uint32_t bB = aB + TILE_B;

        #pragma unroll
        for (int kk = 0; kk < 2; kk++) {
            uint32_t af[2][4];
            #pragma unroll
            for (int mt = 0; mt < 2; mt++)
                ldsm4(af[mt], aB + (uint32_t)((wm * 32 + mt * 16 + ar) * STRIDE + kk * 16 + ak) * 2);
            #pragma unroll
            for (int np = 0; np < 4; np++) {
                uint32_t r[4];
                ldsm4(r, bB + (uint32_t)((wn * 64 + np * 16 + ar) * STRIDE + kk * 16 + ak) * 2);
                uint32_t b0[2] = {r[0], r[2]};
                uint32_t b1[2] = {r[1], r[3]};
                #pragma unroll
                for (int mt = 0; mt < 2; mt++) {
                    mma16816(acc[mt][np * 2],     af[mt], b0);
                    mma16816(acc[mt][np * 2 + 1], af[mt], b1);
                }
            }
        }
    }
}

// ---------------------------------------------------------------------------
// 0. weights fp32 -> bf16
// ---------------------------------------------------------------------------
__global__ __launch_bounds__(256) void prep_kernel(const float* __restrict__ Wq,
                                                   const float* __restrict__ Wk,
                                                   const float* __restrict__ Wv) {
    int i = blockIdx.x * 256 + threadIdx.x;
    float4 a; uint2 u; __nv_bfloat162 h0, h1;
    a = reinterpret_cast<const float4*>(Wq)[i];
    h0 = __floats2bfloat162_rn(a.x, a.y); h1 = __floats2bfloat162_rn(a.z, a.w);
    u.x = *reinterpret_cast<uint32_t*>(&h0); u.y = *reinterpret_cast<uint32_t*>(&h1);
    reinterpret_cast<uint2*>(g_wq)[i] = u;
    a = reinterpret_cast<const float4*>(Wk)[i];
    h0 = __floats2bfloat162_rn(a.x, a.y); h1 = __floats2bfloat162_rn(a.z, a.w);
    u.x = *reinterpret_cast<uint32_t*>(&h0); u.y = *reinterpret_cast<uint32_t*>(&h1);
    reinterpret_cast<uint2*>(g_wk)[i] = u;
    a = reinterpret_cast<const float4*>(Wv)[i];
    h0 = __floats2bfloat162_rn(a.x, a.y); h1 = __floats2bfloat162_rn(a.z, a.w);
    u.x = *reinterpret_cast<uint32_t*>(&h0); u.y = *reinterpret_cast<uint32_t*>(&h1);
    reinterpret_cast<uint2*>(g_wv)[i] = u;
}

// ---------------------------------------------------------------------------
// 1a. GroupNorm stats
// ---------------------------------------------------------------------------
__global__ __launch_bounds__(256) void gn_stats_kernel(const float* __restrict__ x) {
    int s = blockIdx.x, bg = blockIdx.y;
    const float* xp = x + (size_t)bg * GC * N_ + (size_t)s * 8192;
    float sum = 0.f, ss = 0.f;
    #pragma unroll
    for (int i = 0; i < 8; i++) {
        float4 v = reinterpret_cast<const float4*>(xp)[threadIdx.x + i * 256];
        sum += v.x + v.y + v.z + v.w;
        ss  += v.x * v.x + v.y * v.y + v.z * v.z + v.w * v.w;
    }
    __shared__ float sh1[256], sh2[256];
    sh1[threadIdx.x] = sum; sh2[threadIdx.x] = ss;
    __syncthreads();
    for (int o = 128; o > 0; o >>= 1) {
        if (threadIdx.x < o) {
            sh1[threadIdx.x] += sh1[threadIdx.x + o];
            sh2[threadIdx.x] += sh2[threadIdx.x + o];
        }
        __syncthreads();
    }
    if (threadIdx.x == 0) {
        g_red[bg][s][0] = sh1[0];
        g_red[bg][s][1] = sh2[0];
    }
}

// ---------------------------------------------------------------------------
// 1b. GroupNorm apply + transpose: x[b][c][n] -> hT[b][n][c] bf16
// ---------------------------------------------------------------------------
__global__ __launch_bounds__(256) void gn_apply_kernel(const float* __restrict__ x,
                                                       const float* __restrict__ gamma,
                                                       const float* __restrict__ beta) {
    int ns = blockIdx.x, g = blockIdx.y, b = blockIdx.z;
    int bg = b * NG + g;
    float sum = 0.f, ss = 0.f;
    #pragma unroll
    for (int i = 0; i < 8; i++) { sum += g_red[bg][i][0]; ss += g_red[bg][i][1]; }
    const float inv_n = 1.0f / (GC * N_);
    float mean = sum * inv_n;
    float var  = ss * inv_n - mean * mean;
    float rstd = rsqrtf(var + 1e-5f);

    const float* xp = x + (size_t)bg * GC * N_;
    bf16* out = g_hT + (size_t)b * N_ * C_ + g * GC;
    __shared__ float tile[32 * 65];
    int tid = threadIdx.x;
    int nbase = ns * 128;
    for (int n0 = nbase; n0 < nbase + 128; n0 += 32) {
        for (int e = tid; e < GC * 32; e += 256) {
            int c = e >> 5, n = e & 31;
            float v = (xp[(size_t)c * N_ + n0 + n] - mean) * rstd;
            v = v * __ldg(&gamma[g * GC + c]) + __ldg(&beta[g * GC + c]);
            tile[n * 65 + c] = v;
        }
        __syncthreads();
        {
            int n = tid >> 3, u = tid & 7;
            uint32_t pk[4];
            #pragma unroll
            for (int j = 0; j < 4; j++) {
                __nv_bfloat162 h = __floats2bfloat162_rn(tile[n * 65 + u * 8 + 2 * j],
                                                         tile[n * 65 + u * 8 + 2 * j + 1]);
                pk[j] = *reinterpret_cast<uint32_t*>(&h);
            }
            *reinterpret_cast<uint4*>(out + (size_t)(n0 + n) * C_ + u * 8) =
                *reinterpret_cast<uint4*>(pk);
        }
        __syncthreads();
    }
}

// ---------------------------------------------------------------------------
// 2. QKV: out = hT @ W^T + b.  mi=0 -> q (x 1/16), mi=1 -> k, mi=2 -> Vt.
// ---------------------------------------------------------------------------
__global__ __launch_bounds__(256) void qkv_kernel(const float* __restrict__ bq,
                                                  const float* __restrict__ bk,
                                                  const float* __restrict__ bv) {
    extern __shared__ __align__(16) char dsm[];
    int tid = threadIdx.x;
    int mi = blockIdx.z % 3, b = blockIdx.z / 3;
    int n0 = blockIdx.x * 128, m0 = blockIdx.y * 128;
    const bf16* A  = g_hT + (size_t)b * N_ * C_ + (size_t)m0 * C_;
    const bf16* Bm = (mi == 0 ? g_wq : mi == 1 ? g_wk : g_wv) + (size_t)n0 * C_;
    float acc[2][8][4] = {};
    gemm_ms(A, C_, Bm, C_, C_ / KT, dsm, acc, tid);

    int lane = tid & 31, wid = tid >> 5;
    int wm = wid & 3, wn = wid >> 2;
    int quad = lane >> 2, qt = lane & 3;
    const float* bias = (mi == 0) ? bq : (mi == 1) ? bk : bv;

    if (mi < 2) {
        bf16* out = ((mi == 0) ? g_q : g_k) + (size_t)b * N_ * C_;
        float scale = (mi == 0) ? 0.0625f : 1.0f;
        #pragma unroll
        for (int mt = 0; mt < 2; mt++) {
            int r0 = m0 + wm * 32 + mt * 16 + quad;
            #pragma unroll
            for (int nt = 0; nt < 8; nt++) {
                int d = n0 + wn * 64 + nt * 8 + qt * 2;
                float b0 = __ldg(&bias[d]), b1 = __ldg(&bias[d + 1]);
                __nv_bfloat162 h0 = __floats2bfloat162_rn((acc[mt][nt][0] + b0) * scale,
                                                          (acc[mt][nt][1] + b1) * scale);
                __nv_bfloat162 h1 = __floats2bfloat162_rn((acc[mt][nt][2] + b0) * scale,
                                                          (acc[mt][nt][3] + b1) * scale);
                *reinterpret_cast<uint32_t*>(out + (size_t)r0 * C_ + d) =
                    *reinterpret_cast<uint32_t*>(&h0);
                *reinterpret_cast<uint32_t*>(out + (size_t)(r0 + 8) * C_ + d) =
                    *reinterpret_cast<uint32_t*>(&h1);
            }
        }
    } else {
        bf16* st = reinterpret_cast<bf16*>(dsm);   // [256 d][stride 136]
        __syncthreads();
        #pragma unroll
        for (int mt = 0; mt < 2; mt++) {
            int ml = wm * 32 + mt * 16 + quad;
            #pragma unroll
            for (int nt = 0; nt < 8; nt++) {
                int dl = wn * 64 + nt * 8 + qt * 2;
                float b0 = __ldg(&bias[n0 + dl]), b1 = __ldg(&bias[n0 + dl + 1]);
                st[dl * 136 + ml]           = __float2bfloat16_rn(acc[mt][nt][0] + b0);
                st[(dl + 1) * 136 + ml]     = __float2bfloat16_rn(acc[mt][nt][1] + b1);
                st[dl * 136 + ml + 8]       = __float2bfloat16_rn(acc[mt][nt][2] + b0);
                st[(dl + 1) * 136 + ml + 8] = __float2bfloat16_rn(acc[mt][nt][3] + b1);
            }
        }
        __syncthreads();
        bf16* outv = g_vt + (size_t)b * C_ * N_;
        #pragma unroll
        for (int c = 0; c < 8; c++) {
            int id = tid + 256 * c;
            int d = id >> 4, ch = (id & 15) * 8;
            *reinterpret_cast<uint4*>(outv + (size_t)(n0 + d) * N_ + m0 + ch) =
                *reinterpret_cast<uint4*>(st + d * 136 + ch);
        }
    }
}

// ---------------------------------------------------------------------------
// 3. FUSED scores+softmax, 512 threads: warp grid 2(q) x 8(keys).
//    CTA: 32 query rows x full 1024 keys; acc 64 regs/thread.
// ---------------------------------------------------------------------------
#define FS_STAGE ((1024 + 32) * STRIDE * 2)   // 84480 B
#define FS_SMEM  (2 * FS_STAGE)               // 168960 B

__device__ __forceinline__ void fs_copy(const bf16* Q, const bf16* K,
                                        uint32_t sK, uint32_t sQ, int k0, int tid) {
    #pragma unroll
    for (int i = 0; i < 9; i++) {
        int id = tid + 512 * i;
        if (id < 4096) {
            int row = id >> 2, col = (id & 3) * 8;
            cp16(sK + (uint32_t)(row * STRIDE + col) * 2, K + (size_t)row * C_ + k0 + col);
        } else if (id < 4224) {
            int q = id - 4096;
            int row = q >> 2, col = (q & 3) * 8;
            cp16(sQ + (uint32_t)(row * STRIDE + col) * 2, Q + (size_t)row * C_ + k0 + col);
        }
    }
    cp_commit();
}

__global__ __launch_bounds__(512, 1) void score_softmax_kernel() {
    extern __shared__ __align__(16) char dsm[];
    int tid = threadIdx.x;
    int lane = tid & 31, wid = tid >> 5;
    int quad = lane >> 2, qt = lane & 3;
    int wn = wid & 7, wq = wid >> 3;      // key-slice warp, query-half warp
    int b = blockIdx.y, m0 = blockIdx.x * 32;

    const bf16* Q = g_q + ((size_t)b * N_ + m0) * C_;
    const bf16* K = g_k + (size_t)b * N_ * C_;

    uint32_t base = smem_u32(dsm);
    uint32_t sK0 = base, sQ0 = base + 1024 * STRIDE * 2;
    uint32_t sK1 = base + FS_STAGE, sQ1 = sK1 + 1024 * STRIDE * 2;

    float acc[16][4] = {};   // S rows wq*16.., key cols wn*128 + nt*8

    fs_copy(Q, K, sK0, sQ0, 0, tid);
    int ar = lane & 15, ak = (lane >> 4) * 8;
    const int T = C_ / KT;  // 8
    for (int t = 0; t < T; t++) {
        cp_wait0();
        __syncthreads();
        if (t + 1 < T)
            fs_copy(Q, K, (t & 1) ? sK0 : sK1, (t & 1) ? sQ0 : sQ1, (t + 1) * KT, tid);
        else
            cp_commit();
        uint32_t kB = (t & 1) ? sK1 : sK0;
        uint32_t qB = (t & 1) ? sQ1 : sQ0;

        #pragma unroll
        for (int kk = 0; kk < 2; kk++) {
            uint32_t af[4];
            ldsm4(af, qB + (uint32_t)((wq * 16 + ar) * STRIDE + kk * 16 + ak) * 2);
            #pragma unroll
            for (int np = 0; np < 8; np++) {
                uint32_t r[4];
                ldsm4(r, kB + (uint32_t)((wn * 128 + np * 16 + ar) * STRIDE + kk * 16 + ak) * 2);
                uint32_t b0[2] = {r[0], r[2]};
                uint32_t b1[2] = {r[1], r[3]};
                mma16816(acc[np * 2],     af, b0);
                mma16816(acc[np * 2 + 1], af, b1);
            }
        }
    }

    // ---- softmax over rows (keys distributed over 8 wn warps) ----
    float* red  = reinterpret_cast<float*>(dsm);   // [32 rows][8 warps]
    float* red2 = red + 32 * 8;

    float rmax[2] = {-1e30f, -1e30f};
    #pragma unroll
    for (int nt = 0; nt < 16; nt++) {
        rmax[0] = fmaxf(rmax[0], fmaxf(acc[nt][0], acc[nt][1]));
        rmax[1] = fmaxf(rmax[1], fmaxf(acc[nt][2], acc[nt][3]));
    }
    #pragma unroll
    for (int h = 0; h < 2; h++) {
        rmax[h] = fmaxf(rmax[h], __shfl_xor_sync(0xffffffffu, rmax[h], 1));
        rmax[h] = fmaxf(rmax[h], __shfl_xor_sync(0xffffffffu, rmax[h], 2));
    }
    if (qt == 0) {
        red[(wq * 16 + quad) * 8 + wn]     = rmax[0];
        red[(wq * 16 + 8 + quad) * 8 + wn] = rmax[1];
    }
    __syncthreads();
    float M[2];
    #pragma unroll
    for (int h = 0; h < 2; h++) {
        float m = -1e30f;
        #pragma unroll
        for (int w8 = 0; w8 < 8; w8++) m = fmaxf(m, red[(wq * 16 + h * 8 + quad) * 8 + w8]);
        M[h] = m;
    }

    float rsum[2] = {0.f, 0.f};
    #pragma unroll
    for (int nt = 0; nt < 16; nt++) {
        acc[nt][0] = __expf(acc[nt][0] - M[0]);
        acc[nt][1] = __expf(acc[nt][1] - M[0]);
        acc[nt][2] = __expf(acc[nt][2] - M[1]);
        acc[nt][3] = __expf(acc[nt][3] - M[1]);
        rsum[0] += acc[nt][0] + acc[nt][1];
        rsum[1] += acc[nt][2] + acc[nt][3];
    }
    #pragma unroll
    for (int h = 0; h < 2; h++) {
        rsum[h] += __shfl_xor_sync(0xffffffffu, rsum[h], 1);
        rsum[h] += __shfl_xor_sync(0xffffffffu, rsum[h], 2);
    }
    if (qt == 0) {
        red2[(wq * 16 + quad) * 8 + wn]     = rsum[0];
        red2[(wq * 16 + 8 + quad) * 8 + wn] = rsum[1];
    }
    __syncthreads();
    float inv[2];
    #pragma unroll
    for (int h = 0; h < 2; h++) {
        float s = 0.f;
        #pragma unroll
        for (int w8 = 0; w8 < 8; w8++) s += red2[(wq * 16 + h * 8 + quad) * 8 + w8];
        inv[h] = 1.0f / s;
    }

    bf16* P = g_p + (size_t)b * N_ * N_;
    int r0 = m0 + wq * 16 + quad;
    #pragma unroll
    for (int nt = 0; nt < 16; nt++) {
        int cc = wn * 128 + nt * 8 + qt * 2;
        __nv_bfloat162 h0 = __floats2bfloat162_rn(acc[nt][0] * inv[0], acc[nt][1] * inv[0]);
        __nv_bfloat162 h1 = __floats2bfloat162_rn(acc[nt][2] * inv[1], acc[nt][3] * inv[1]);
        *reinterpret_cast<uint32_t*>(P + (size_t)r0 * N_ + cc) = *reinterpret_cast<uint32_t*>(&h0);
        *reinterpret_cast<uint32_t*>(P + (size_t)(r0 + 8) * N_ + cc) = *reinterpret_cast<uint32_t*>(&h1);
    }
}

// ---------------------------------------------------------------------------
// 5. PV as O^T: out[b][c][n] = sum_m Vt[b][c][m] * P[b][n][m] + x[b][c][n]
// ---------------------------------------------------------------------------
__global__ __launch_bounds__(256) void pv_kernel(const float* __restrict__ x,
                                                 float* __restrict__ outp) {
    extern __shared__ __align__(16) char dsm[];
    int tid = threadIdx.x;
    int b = blockIdx.z;
    int n0 = blockIdx.x * 128;   // token tile
    int m0 = blockIdx.y * 128;   // channel tile
    const bf16* A  = g_vt + (size_t)b * C_ * N_ + (size_t)m0 * N_;
    const bf16* Bm = g_p  + (size_t)b * N_ * N_ + (size_t)n0 * N_;
    float acc[2][8][4] = {};
    gemm_ms(A, N_, Bm, N_, N_ / KT, dsm, acc, tid);

    int lane = tid & 31, wid = tid >> 5;
    int wm = wid & 3, wn = wid >> 2;
    int quad = lane >> 2, qt = lane & 3;
    #pragma unroll
    for (int mt = 0; mt < 2; mt++) {
        int cg = m0 + wm * 32 + mt * 16 + quad;
        #pragma unroll
        for (int nt = 0; nt < 8; nt++) {
            int ng = n0 + wn * 64 + nt * 8 + qt * 2;
            size_t base = ((size_t)b * C_ + cg) * N_ + ng;
            float2 xv = *reinterpret_cast<const float2*>(x + base);
            *reinterpret_cast<float2*>(outp + base) =
                make_float2(acc[mt][nt][0] + xv.x, acc[mt][nt][1] + xv.y);
            size_t base8 = base + (size_t)8 * N_;
            float2 xv8 = *reinterpret_cast<const float2*>(x + base8);
            *reinterpret_cast<float2*>(outp + base8) =
                make_float2(acc[mt][nt][2] + xv8.x, acc[mt][nt][3] + xv8.y);
        }
    }
}

// ---------------------------------------------------------------------------
extern "C" void kernel_launch(void* const* d_in, const int* in_sizes, int n_in,
                              void* d_out, int out_size) {
    const float* x     = (const float*)d_in[0];
    const float* Wq    = (const float*)d_in[1];
    const float* bq    = (const float*)d_in[2];
    const float* Wk    = (const float*)d_in[3];
    const float* bk    = (const float*)d_in[4];
    const float* Wv    = (const float*)d_in[5];
    const float* bv    = (const float*)d_in[6];
    const float* gamma = (const float*)d_in[7];
    const float* beta  = (const float*)d_in[8];
    float* out = (float*)d_out;

    cudaFuncSetAttribute(qkv_kernel, cudaFuncAttributeMaxDynamicSharedMemorySize, GEMM_SMEM);
    cudaFuncSetAttribute(pv_kernel, cudaFuncAttributeMaxDynamicSharedMemorySize, GEMM_SMEM);
    cudaFuncSetAttribute(score_softmax_kernel, cudaFuncAttributeMaxDynamicSharedMemorySize, FS_SMEM);

    prep_kernel<<<64, 256>>>(Wq, Wk, Wv);
    gn_stats_kernel<<<dim3(8, B_ * NG), 256>>>(x);
    gn_apply_kernel<<<dim3(8, NG, B_), 256>>>(x, gamma, beta);
    qkv_kernel<<<dim3(2, 8, 3 * B_), 256, GEMM_SMEM>>>(bq, bk, bv);
    score_softmax_kernel<<<dim3(32, B_), 512, FS_SMEM>>>();
    pv_kernel<<<dim3(8, 2, B_), 256, GEMM_SMEM>>>(x, out);
}